// round 12
// baseline (speedup 1.0000x reference)
#include <cuda_runtime.h>
#include <stdint.h>

// Transducer loss: unnormalized linear-domain fp32 recurrence.
// R12: each batch split across 2 warps (4 labels/lane) on different SMSPs of
// one SM; seam label passed via smem ring with 1-macro logical skew; renorm
// cadence 8 steps, pin 2^-20, -48 bounded-diff clamp + adoption (R7-proven).

#define INV_LN2 1.44269504088896340736f
#define LN2_F   0.69314718055994530942f

static constexpr int B  = 128;
static constexpr int T  = 2000;
static constexpr int C  = 62;
static constexpr int L  = 256;

typedef unsigned int u32;

__device__ float g_prob[B * T * C + 32 * C];  // padded for prefetch overshoot
__device__ float g_lgs[B * T];                // log2 of per-row sum
__device__ float g_bloss[B];

static __device__ __forceinline__ float ex2f(float x) {
    float y; asm("ex2.approx.ftz.f32 %0, %1;" : "=f"(y) : "f"(x)); return y;
}
static __device__ __forceinline__ float lg2f(float x) {
    float y; asm("lg2.approx.ftz.f32 %0, %1;" : "=f"(y) : "f"(x)); return y;
}
static __device__ __forceinline__ float p2f(int e) {   // 2^e, e in [-126,127]
    return __uint_as_float((u32)(127 + e) << 23);
}

// ---------------------------------------------------------------------------
// K1: streaming map + fused rowsums, float4 vectorized. (At LTS cap.)
// ---------------------------------------------------------------------------
__global__ __launch_bounds__(256) void prob_kernel(const float* __restrict__ x) {
    __shared__ float sp[32 * C];
    const long base = (long)blockIdx.x * (32 * C);
    const float4* xv = (const float4*)(x + base);
    float4* pv = (float4*)(g_prob + base);

#pragma unroll
    for (int it = 0; it < 2; it++) {
        const int i = threadIdx.x + it * 256;
        if (i < (32 * C) / 4) {
            const float4 v = __ldg(xv + i);
            float4 p;
            p.x = ex2f(v.x * INV_LN2);
            p.y = ex2f(v.y * INV_LN2);
            p.z = ex2f(v.z * INV_LN2);
            p.w = ex2f(v.w * INV_LN2);
            pv[i] = p;
            *(float4*)(sp + 4 * i) = p;
        }
    }
    __syncthreads();

    const int r = threadIdx.x >> 3;
    const int k = threadIdx.x & 7;
    float s = 0.f;
    const int off = r * C + k * 8;
#pragma unroll
    for (int i = 0; i < 8; i++)
        if (k * 8 + i < C) s += sp[off + i];
    s += __shfl_xor_sync(0xffffffffu, s, 4);
    s += __shfl_xor_sync(0xffffffffu, s, 2);
    s += __shfl_xor_sync(0xffffffffu, s, 1);
    if (k == 0) g_lgs[blockIdx.x * 32 + r] = lg2f(s);
}

// ---------------------------------------------------------------------------
// K2: the recurrence. 2 warps per batch; warp w owns labels w*128..w*128+127,
// 4 labels per lane. Warp1 runs one 8-step macro behind warp0 (seam ring).
// ---------------------------------------------------------------------------
__global__ __launch_bounds__(64, 1) void recur_kernel(const int* __restrict__ tg) {
    const int b = blockIdx.x;
    const int tid = threadIdx.x;
    const int wid = tid >> 5;
    const int lane = tid & 31;

    __shared__ float sbuf[4][8][64];   // staging ring: 4 macros x 8 rows
    __shared__ float sring_val[2][8];  // warp0 lane31 pre-step S[3], per macro parity
    __shared__ int   sring_tb[2];      // warp0 lane31 tentative base at COMP
    __shared__ int   sring_bg[2];      // warp0 lane31 base after APPLY
    __shared__ float scorr;

    const float* prow = g_prob + (long)b * T * C;

    // ---- normalization correction: warp w sums its half ----
    float corr = 0.f;
    {
        const float4* lgv = (const float4*)(g_lgs + b * T);
        for (int i = wid * 250 + lane; i < wid * 250 + 250; i += 32) {
            const float4 v = __ldg(lgv + i);
            corr += (v.x + v.y) + (v.z + v.w);
        }
    }
#pragma unroll
    for (int o = 16; o; o >>= 1) corr += __shfl_xor_sync(0xffffffffu, corr, o);
    if (wid == 0 && lane == 0) scorr = corr;

    // ---- gather targets: labels wid*128 + lane*4 + j ----
    float* ap[4];
    int tgt0 = 0;
#pragma unroll
    for (int j = 0; j < 4; j++) {
        const int tc = __ldg(tg + b * L + wid * 128 + lane * 4 + j);
        if (j == 0) tgt0 = tc;
        ap[j] = &sbuf[0][0][tc];
    }

    // ---- prologue staging: warp w stages macro w (rows t=8w+1..8w+8) ----
#pragma unroll
    for (int s = 0; s < 8; s++) {
        const float2 v = *(const float2*)(prow + (8 * wid + 1 + s) * C + 2 * lane);
        *(float2*)&sbuf[wid][s][2 * lane] = v;
    }
    float2 R[8];
    if (wid == 0) {
#pragma unroll
        for (int s = 0; s < 8; s++)
            R[s] = *(const float2*)(prow + (17 + s) * C + 2 * lane);   // macro 2
    }
    const float2* pr = (const float2*)(prow + 25 * C) + lane;          // macro 3
    __syncthreads();

    float G0[4], G1[4];
#pragma unroll
    for (int j = 0; j < 4; j++) G0[j] = ap[j][0];   // macro0 slot0 (t=1)

    float S[4] = {0.f, 0.f, 0.f, 0.f};
    if (wid == 0 && lane == 0) S[0] = __ldg(prow + tgt0);   // t=0 init

    int base = 0;
    float c1 = (wid == 0 && lane == 0) ? 0.f : 1.f;
    float c2 = 1.f;
    float pf1 = 1.f, pf2 = 1.f;
    int pnb = 0;

#define GOFF(BUF, SLOT) (((BUF) * 8 + (SLOT)) * 64)

#define STEPX(Wf, GC, GN, OFFN, RNG, KK)                                       \
    do {                                                                        \
        float cr = __shfl_up_sync(0xffffffffu, S[3], 1);                        \
        if (Wf) { if (lane == 0) cr = sring_val[RNG][KK]; }                     \
        else    { if (lane == 31) sring_val[RNG][KK] = S[3]; }                  \
        cr = cr * c1 * c2;                                                      \
        S[3] = (S[3] + S[2]) * GC[3];                                           \
        S[2] = (S[2] + S[1]) * GC[2];                                           \
        S[1] = (S[1] + S[0]) * GC[1];                                           \
        S[0] = (S[0] + cr) * GC[0];                                             \
        GN[0] = ap[0][OFFN]; GN[1] = ap[1][OFFN];                               \
        GN[2] = ap[2][OFFN]; GN[3] = ap[3][OFFN];                               \
    } while (0)

#define STEPNP(Wf, GC, RNG, KK)                                                \
    do {                                                                        \
        float cr = __shfl_up_sync(0xffffffffu, S[3], 1);                        \
        if (Wf) { if (lane == 0) cr = sring_val[RNG][KK]; }                     \
        else    { if (lane == 31) sring_val[RNG][KK] = S[3]; }                  \
        cr = cr * c1 * c2;                                                      \
        S[3] = (S[3] + S[2]) * GC[3];                                           \
        S[2] = (S[2] + S[1]) * GC[2];                                           \
        S[1] = (S[1] + S[0]) * GC[1];                                           \
        S[0] = (S[0] + cr) * GC[0];                                             \
    } while (0)

#define RCOMP(Wf, RNG)                                                          \
    do {                                                                        \
        u32 mx = __float_as_uint(S[0]);                                         \
        mx = max(mx, __float_as_uint(S[1]));                                    \
        mx = max(mx, __float_as_uint(S[2]));                                    \
        mx = max(mx, __float_as_uint(S[3]));                                    \
        const int e = (int)(mx >> 23);                                          \
        const int d = min(127, max(-126, 107 - e));  /* pin max to 2^-20 */     \
        const int tb = (mx == 0u) ? base : (base - d);                          \
        if (!(Wf)) { if (lane == 31) sring_tb[RNG] = tb; }                      \
        int bp = __shfl_up_sync(0xffffffffu, tb, 1);                            \
        if (Wf) { if (lane == 0) bp = sring_tb[RNG]; }                          \
        int nb = tb;                                                            \
        if ((Wf) || lane > 0) nb = (mx == 0u) ? bp : max(tb, bp - 48);          \
        const int sh = base - nb;                                               \
        const int s1 = min(127, max(-126, sh));                                 \
        const int s2 = min(127, max(-126, sh - s1));                            \
        pf1 = p2f(s1); pf2 = p2f(s2); pnb = nb;                                 \
    } while (0)

#define RAPPLY(Wf, RNG)                                                         \
    do {                                                                        \
        S[0] = S[0] * pf1 * pf2; S[1] = S[1] * pf1 * pf2;                       \
        S[2] = S[2] * pf1 * pf2; S[3] = S[3] * pf1 * pf2;                       \
        base = pnb;                                                             \
        if (!(Wf)) { if (lane == 31) sring_bg[RNG] = base; }                    \
        int bpf = __shfl_up_sync(0xffffffffu, base, 1);                         \
        if (Wf) { if (lane == 0) bpf = sring_bg[RNG]; }                         \
        const int diff = bpf - base;                                            \
        int d1 = diff >> 1;                                                     \
        int d2 = diff - d1;                                                     \
        d1 = min(126, max(-126, d1)); d2 = min(126, max(-126, d2));             \
        c1 = (!(Wf) && lane == 0) ? 0.f : p2f(d1);                              \
        c2 = p2f(d2);                                                           \
    } while (0)

#define STAGE(SB)                                                               \
    do {                                                                        \
        _Pragma("unroll")                                                       \
        for (int s = 0; s < 8; s++)                                             \
            *(float2*)&sbuf[SB][s][2 * lane] = R[s];                            \
        _Pragma("unroll")                                                       \
        for (int s = 0; s < 8; s++) R[s] = __ldg(pr + s * 31);                  \
        pr += 248;                                                              \
    } while (0)

#define PROC(Wf, BUF, RNG, NXT)                                                 \
    do {                                                                        \
        STEPX(Wf, G0, G1, GOFF(BUF, 1), RNG, 0);                                \
        STEPX(Wf, G1, G0, GOFF(BUF, 2), RNG, 1);                                \
        STEPX(Wf, G0, G1, GOFF(BUF, 3), RNG, 2);                                \
        STEPX(Wf, G1, G0, GOFF(BUF, 4), RNG, 3);                                \
        STEPX(Wf, G0, G1, GOFF(BUF, 5), RNG, 4);                                \
        STEPX(Wf, G1, G0, GOFF(BUF, 6), RNG, 5);  RCOMP(Wf, RNG);               \
        STEPX(Wf, G0, G1, GOFF(BUF, 7), RNG, 6);                                \
        STEPX(Wf, G1, G0, GOFF(NXT, 0), RNG, 7);  RAPPLY(Wf, RNG);              \
    } while (0)

#define PROC_TAIL(Wf, BUF, RNG)                                                 \
    do {                                                                        \
        STEPX(Wf, G0, G1, GOFF(BUF, 1), RNG, 0);                                \
        STEPX(Wf, G1, G0, GOFF(BUF, 2), RNG, 1);                                \
        STEPX(Wf, G0, G1, GOFF(BUF, 3), RNG, 2);                                \
        STEPX(Wf, G1, G0, GOFF(BUF, 4), RNG, 3);                                \
        STEPX(Wf, G0, G1, GOFF(BUF, 5), RNG, 4);                                \
        STEPX(Wf, G1, G0, GOFF(BUF, 6), RNG, 5);                                \
        STEPNP(Wf, G0, RNG, 6);                                                 \
    } while (0)

// iteration it: warp0 processes macro it, warp1 processes macro it-1.
#define ITER(K)                                                                 \
    do {                                                                        \
        if (wid == 0) {                                                         \
            STAGE(((K) + 2) & 3);                                               \
            PROC(0, (K), (K) & 1, ((K) + 1) & 3);                               \
        } else {                                                                \
            PROC(1, ((K) + 3) & 3, ((K) + 1) & 1, (K));                         \
        }                                                                       \
        __syncthreads();                                                        \
    } while (0)

    // it = 0: warp1 idle.
    if (wid == 0) { STAGE(2); PROC(0, 0, 0, 1); }
    __syncthreads();
    ITER(1); ITER(2); ITER(3);
    // it = 4..247
    for (int mm = 0; mm < 61; mm++) { ITER(0); ITER(1); ITER(2); ITER(3); }
    // it = 248 (no staging needed beyond macro 249)
    if (wid == 0) { PROC(0, 0, 0, 1); }
    else          { PROC(1, 3, 1, 0); }
    __syncthreads();
    // it = 249: warp0 tail (macro 249, 7 steps), warp1 full macro 248
    if (wid == 0) { PROC_TAIL(0, 1, 1); }
    else          { PROC(1, 0, 0, 1); }
    __syncthreads();
    // it = 250: warp1 tail (macro 249)
    if (wid == 1) { PROC_TAIL(1, 1, 1); }
    __syncthreads();

    if (wid == 1 && lane == 31) {
        const float alpha2 = lg2f(S[3]) + (float)base;      // raw log2 alpha[255]
        g_bloss[b] = (scorr + corr - alpha2) * LN2_F;       // normalize, nats
    }
#undef GOFF
#undef STEPX
#undef STEPNP
#undef RCOMP
#undef RAPPLY
#undef STAGE
#undef PROC
#undef PROC_TAIL
#undef ITER
}

// ---------------------------------------------------------------------------
// K3: deterministic mean over the batch.
// ---------------------------------------------------------------------------
__global__ __launch_bounds__(128) void reduce_kernel(float* __restrict__ out) {
    const int i = threadIdx.x;
    float v = g_bloss[i];
#pragma unroll
    for (int o = 16; o; o >>= 1) v += __shfl_xor_sync(0xffffffffu, v, o);
    __shared__ float ws[4];
    if ((i & 31) == 0) ws[i >> 5] = v;
    __syncthreads();
    if (i == 0) out[0] = (ws[0] + ws[1] + ws[2] + ws[3]) * (1.0f / (float)B);
}

// ---------------------------------------------------------------------------
extern "C" void kernel_launch(void* const* d_in, const int* in_sizes, int n_in,
                              void* d_out, int out_size) {
    const float* x = (const float*)d_in[0];   // [B, T, C] float32
    const int* tg = (const int*)d_in[1];      // [B, L] int32
    float* out = (float*)d_out;

    (void)in_sizes; (void)n_in; (void)out_size;

    prob_kernel<<<(B * T) / 32, 256>>>(x);
    recur_kernel<<<B, 64>>>(tg);
    reduce_kernel<<<1, 128>>>(out);
}

// round 14
// speedup vs baseline: 1.3271x; 1.3271x over previous
#include <cuda_runtime.h>
#include <stdint.h>

// Transducer loss: unnormalized linear-domain fp32 recurrence.
// R14: R11's proven renorm schedule (cadence 4, pin 2^0, -48 clamp, adoption,
// deferred COMPUTE->APPLY) with packed f32x2 state math and folded carry
// factor. Staging/gather path identical to R11.

#define INV_LN2 1.44269504088896340736f
#define LN2_F   0.69314718055994530942f

static constexpr int B  = 128;
static constexpr int T  = 2000;
static constexpr int C  = 62;
static constexpr int L  = 256;

typedef unsigned long long ull;
typedef unsigned int u32;

__device__ float g_prob[B * T * C + 32 * C];  // padded for prefetch overshoot
__device__ float g_lgs[B * T];                // log2 of per-row sum
__device__ float g_bloss[B];

static __device__ __forceinline__ float ex2f(float x) {
    float y; asm("ex2.approx.ftz.f32 %0, %1;" : "=f"(y) : "f"(x)); return y;
}
static __device__ __forceinline__ float lg2f(float x) {
    float y; asm("lg2.approx.ftz.f32 %0, %1;" : "=f"(y) : "f"(x)); return y;
}
static __device__ __forceinline__ float p2f(int e) {   // 2^e, e in [-126,127]
    return __uint_as_float((u32)(127 + e) << 23);
}
static __device__ __forceinline__ ull pk(float lo, float hi) {
    ull r; asm("mov.b64 %0, {%1, %2};" : "=l"(r) : "f"(lo), "f"(hi)); return r;
}
static __device__ __forceinline__ void upk(ull v, float& lo, float& hi) {
    asm("mov.b64 {%0, %1}, %2;" : "=f"(lo), "=f"(hi) : "l"(v));
}
static __device__ __forceinline__ ull add2(ull a, ull b) {
    ull r; asm("add.rn.f32x2 %0, %1, %2;" : "=l"(r) : "l"(a), "l"(b)); return r;
}
static __device__ __forceinline__ ull mul2(ull a, ull b) {
    ull r; asm("mul.rn.f32x2 %0, %1, %2;" : "=l"(r) : "l"(a), "l"(b)); return r;
}

// ---------------------------------------------------------------------------
// K1: streaming map + fused rowsums, float4 vectorized. (At LTS cap.)
// ---------------------------------------------------------------------------
__global__ __launch_bounds__(256) void prob_kernel(const float* __restrict__ x) {
    __shared__ float sp[32 * C];
    const long base = (long)blockIdx.x * (32 * C);
    const float4* xv = (const float4*)(x + base);
    float4* pv = (float4*)(g_prob + base);

#pragma unroll
    for (int it = 0; it < 2; it++) {
        const int i = threadIdx.x + it * 256;
        if (i < (32 * C) / 4) {
            const float4 v = __ldg(xv + i);
            float4 p;
            p.x = ex2f(v.x * INV_LN2);
            p.y = ex2f(v.y * INV_LN2);
            p.z = ex2f(v.z * INV_LN2);
            p.w = ex2f(v.w * INV_LN2);
            pv[i] = p;
            *(float4*)(sp + 4 * i) = p;
        }
    }
    __syncthreads();

    const int r = threadIdx.x >> 3;
    const int k = threadIdx.x & 7;
    float s = 0.f;
    const int off = r * C + k * 8;
#pragma unroll
    for (int i = 0; i < 8; i++)
        if (k * 8 + i < C) s += sp[off + i];
    s += __shfl_xor_sync(0xffffffffu, s, 4);
    s += __shfl_xor_sync(0xffffffffu, s, 2);
    s += __shfl_xor_sync(0xffffffffu, s, 1);
    if (k == 0) g_lgs[blockIdx.x * 32 + r] = lg2f(s);
}

// ---------------------------------------------------------------------------
// K2: the recurrence. One warp per batch. State pairs (S0S1)..(S6S7) as f32x2.
// ---------------------------------------------------------------------------
__global__ __launch_bounds__(32, 1) void recur_kernel(const int* __restrict__ tg) {
    const int b = blockIdx.x;
    const int lane = threadIdx.x;

    __shared__ float sbuf[2][16][64];   // [buf][slot][padded row]

    const float* prow = g_prob + (long)b * T * C;

    // Time-invariant gather addresses.
    float* ap[8];
    int tgt0 = 0;
#pragma unroll
    for (int j = 0; j < 8; j++) {
        const int tc = __ldg(tg + b * L + lane * 8 + j);
        if (j == 0) tgt0 = tc;
        ap[j] = &sbuf[0][0][tc];
    }

    // ---- prologue: stage macro0 (t=1..16) into buf0; R <- macro1 (t=17..32)
    float2 R[16];
#pragma unroll
    for (int s = 0; s < 16; s++)
        R[s] = *(const float2*)(prow + (1 + s) * C + 2 * lane);
#pragma unroll
    for (int s = 0; s < 16; s++)
        *(float2*)&sbuf[0][s][2 * lane] = R[s];
#pragma unroll
    for (int s = 0; s < 16; s++)
        R[s] = *(const float2*)(prow + (17 + s) * C + 2 * lane);
    const float2* pr = (const float2*)(prow + 33 * C + 2 * lane);
    __syncwarp();

    // ---- fused normalization-correction partial sum (off critical path) ----
    float corr = 0.f;
    {
        const float4* lgv = (const float4*)(g_lgs + b * T);
#pragma unroll 4
        for (int i = lane; i < T / 4; i += 32) {
            const float4 v = __ldg(lgv + i);
            corr += (v.x + v.y) + (v.z + v.w);
        }
    }

    float G0[8], G1[8];
#pragma unroll
    for (int j = 0; j < 8; j++) G0[j] = ap[j][0];    // t=1 gathers

    ull v0 = 0ull, v1 = 0ull, v2 = 0ull, v3 = 0ull;
    if (lane == 0) v0 = pk(__ldg(prow + tgt0), 0.f);   // t = 0 init

    int base = 0;                              // true = S * 2^base, per lane
    float cc = (lane == 0) ? 0.f : 1.f;        // folded carry factor
    float pf1 = 1.f, pf2 = 1.f;                // pending renorm scale
    int pnb = 0;

#define STEP(GC, GN, NW)                                                       \
    do {                                                                        \
        float lo0, hi0, lo1, hi1, lo2, hi2, lo3, hi3;                           \
        upk(v0, lo0, hi0); upk(v1, lo1, hi1);                                   \
        upk(v2, lo2, hi2); upk(v3, lo3, hi3);                                   \
        const float cr = __shfl_up_sync(0xffffffffu, hi3, 1) * cc;              \
        v0 = mul2(add2(v0, pk(cr,  lo0)), pk(GC[0], GC[1]));                    \
        v1 = mul2(add2(v1, pk(hi0, lo1)), pk(GC[2], GC[3]));                    \
        v2 = mul2(add2(v2, pk(hi1, lo2)), pk(GC[4], GC[5]));                    \
        v3 = mul2(add2(v3, pk(hi2, lo3)), pk(GC[6], GC[7]));                    \
        GN[0] = ap[0][NW]; GN[1] = ap[1][NW];                                   \
        GN[2] = ap[2][NW]; GN[3] = ap[3][NW];                                   \
        GN[4] = ap[4][NW]; GN[5] = ap[5][NW];                                   \
        GN[6] = ap[6][NW]; GN[7] = ap[7][NW];                                   \
    } while (0)

#define STEP_NP(GC)                                                            \
    do {                                                                        \
        float lo0, hi0, lo1, hi1, lo2, hi2, lo3, hi3;                           \
        upk(v0, lo0, hi0); upk(v1, lo1, hi1);                                   \
        upk(v2, lo2, hi2); upk(v3, lo3, hi3);                                   \
        const float cr = __shfl_up_sync(0xffffffffu, hi3, 1) * cc;              \
        v0 = mul2(add2(v0, pk(cr,  lo0)), pk(GC[0], GC[1]));                    \
        v1 = mul2(add2(v1, pk(hi0, lo1)), pk(GC[2], GC[3]));                    \
        v2 = mul2(add2(v2, pk(hi1, lo2)), pk(GC[4], GC[5]));                    \
        v3 = mul2(add2(v3, pk(hi2, lo3)), pk(GC[6], GC[7]));                    \
    } while (0)

// COMPUTE: derive pending scale/base. Pin lane max at 2^0 (e=127) — R11 exact.
#define RCOMP()                                                                 \
    do {                                                                        \
        float xa, xb; u32 m;                                                    \
        upk(v0, xa, xb); m = max(__float_as_uint(xa), __float_as_uint(xb));     \
        upk(v1, xa, xb); m = max(m, max(__float_as_uint(xa), __float_as_uint(xb))); \
        upk(v2, xa, xb); m = max(m, max(__float_as_uint(xa), __float_as_uint(xb))); \
        upk(v3, xa, xb); m = max(m, max(__float_as_uint(xa), __float_as_uint(xb))); \
        const int e = (int)(m >> 23);                                           \
        const int d = min(127, max(-126, 127 - e));                             \
        const int tb = (m == 0u) ? base : (base - d);                           \
        const int bp = __shfl_up_sync(0xffffffffu, tb, 1);                      \
        int nb = tb;                                                            \
        if (lane > 0) nb = (m == 0u) ? bp : max(tb, bp - 48);                   \
        const int sh = base - nb;                                               \
        const int s1 = min(127, max(-126, sh));                                 \
        const int s2 = min(127, max(-126, sh - s1));                            \
        pf1 = p2f(s1); pf2 = p2f(s2); pnb = nb;                                 \
    } while (0)

// APPLY: rescale state, commit base, rebuild folded carry factor.
#define RAPPLY()                                                                \
    do {                                                                        \
        const ull z1 = pk(pf1, pf1), z2 = pk(pf2, pf2);                         \
        v0 = mul2(mul2(v0, z1), z2); v1 = mul2(mul2(v1, z1), z2);               \
        v2 = mul2(mul2(v2, z1), z2); v3 = mul2(mul2(v3, z1), z2);               \
        base = pnb;                                                             \
        const int bpf = __shfl_up_sync(0xffffffffu, base, 1);                   \
        const int diff = bpf - base;       /* <= +48 by clamp invariant */      \
        int d1 = diff >> 1;                                                     \
        int d2 = diff - d1;                                                     \
        d1 = min(126, max(-126, d1)); d2 = min(126, max(-126, d2));             \
        cc = (lane == 0) ? 0.f : p2f(d1) * p2f(d2);                             \
    } while (0)

// 16-step macro: STS macro m+1 rows, LDG macro m+2 into R; renorm cadence 4
// (RCOMP after steps 2,6,10,14; RAPPLY after steps 4,8,12,16) — R11 schedule.
#define MACRO16(mbuf)                                                           \
    do {                                                                        \
        _Pragma("unroll")                                                       \
        for (int s = 0; s < 16; s++)                                            \
            *(float2*)&sbuf[1 - (mbuf)][s][2 * lane] = R[s];                    \
        _Pragma("unroll")                                                       \
        for (int s = 0; s < 16; s++) R[s] = __ldg(pr + s * 31);                 \
        pr += 16 * 31;                                                          \
        __syncwarp();                                                           \
        STEP(G0, G1, ((mbuf) * 16 + 1) * 64);                                   \
        STEP(G1, G0, ((mbuf) * 16 + 2) * 64);  RCOMP();                         \
        STEP(G0, G1, ((mbuf) * 16 + 3) * 64);                                   \
        STEP(G1, G0, ((mbuf) * 16 + 4) * 64);  RAPPLY();                        \
        STEP(G0, G1, ((mbuf) * 16 + 5) * 64);                                   \
        STEP(G1, G0, ((mbuf) * 16 + 6) * 64);  RCOMP();                         \
        STEP(G0, G1, ((mbuf) * 16 + 7) * 64);                                   \
        STEP(G1, G0, ((mbuf) * 16 + 8) * 64);  RAPPLY();                        \
        STEP(G0, G1, ((mbuf) * 16 + 9) * 64);                                   \
        STEP(G1, G0, ((mbuf) * 16 + 10) * 64); RCOMP();                         \
        STEP(G0, G1, ((mbuf) * 16 + 11) * 64);                                  \
        STEP(G1, G0, ((mbuf) * 16 + 12) * 64); RAPPLY();                        \
        STEP(G0, G1, ((mbuf) * 16 + 13) * 64);                                  \
        STEP(G1, G0, ((mbuf) * 16 + 14) * 64); RCOMP();                         \
        STEP(G0, G1, ((mbuf) * 16 + 15) * 64);                                  \
        STEP(G1, G0, ((1 - (mbuf)) * 16) * 64); RAPPLY();                       \
    } while (0)

    // Macros m = 0..123 cover t = 1..1984.
    for (int mm = 0; mm < 62; mm++) { MACRO16(0); MACRO16(1); }

    // Tail: t = 1985..1999 (15 steps) from buf0 — R11 schedule.
    STEP(G0, G1, 1 * 64);
    STEP(G1, G0, 2 * 64);   RCOMP();
    STEP(G0, G1, 3 * 64);
    STEP(G1, G0, 4 * 64);   RAPPLY();
    STEP(G0, G1, 5 * 64);
    STEP(G1, G0, 6 * 64);   RCOMP();
    STEP(G0, G1, 7 * 64);
    STEP(G1, G0, 8 * 64);   RAPPLY();
    STEP(G0, G1, 9 * 64);
    STEP(G1, G0, 10 * 64);  RCOMP();
    STEP(G0, G1, 11 * 64);
    STEP(G1, G0, 12 * 64);  RAPPLY();
    STEP(G0, G1, 13 * 64);
    STEP(G1, G0, 14 * 64);
    STEP_NP(G0);

    // reduce correction across lanes (deterministic tree)
#pragma unroll
    for (int o = 16; o; o >>= 1) corr += __shfl_xor_sync(0xffffffffu, corr, o);

    if (lane == 31) {
        float s7lo, s7hi; upk(v3, s7lo, s7hi);
        const float alpha2 = lg2f(s7hi) + (float)base;     // raw log2 alpha
        g_bloss[b] = (corr - alpha2) * LN2_F;              // normalize, nats
    }
#undef STEP
#undef STEP_NP
#undef RCOMP
#undef RAPPLY
#undef MACRO16
}

// ---------------------------------------------------------------------------
// K3: deterministic mean over the batch.
// ---------------------------------------------------------------------------
__global__ __launch_bounds__(128) void reduce_kernel(float* __restrict__ out) {
    const int i = threadIdx.x;
    float v = g_bloss[i];
#pragma unroll
    for (int o = 16; o; o >>= 1) v += __shfl_xor_sync(0xffffffffu, v, o);
    __shared__ float ws[4];
    if ((i & 31) == 0) ws[i >> 5] = v;
    __syncthreads();
    if (i == 0) out[0] = (ws[0] + ws[1] + ws[2] + ws[3]) * (1.0f / (float)B);
}

// ---------------------------------------------------------------------------
extern "C" void kernel_launch(void* const* d_in, const int* in_sizes, int n_in,
                              void* d_out, int out_size) {
    const float* x = (const float*)d_in[0];   // [B, T, C] float32
    const int* tg = (const int*)d_in[1];      // [B, L] int32
    float* out = (float*)d_out;

    (void)in_sizes; (void)n_in; (void)out_size;

    prob_kernel<<<(B * T) / 32, 256>>>(x);
    recur_kernel<<<B, 32>>>(tg);
    reduce_kernel<<<1, 128>>>(out);
}